// round 8
// baseline (speedup 1.0000x reference)
#include <cuda_runtime.h>
#include <cuda_fp16.h>
#include <math.h>
#include <stdint.h>

#define BATCH 1024
#define INF   256
#define OUTF  256
#define NBF   9
#define KD    2304          // NBF * INF; k = n*INF + i
#define BK    32
#define NT    72            // 2304/32 full-K iterations
#define BM 64
#define BN 32
#define NSTAGE 4

// ---- scratch (__device__ globals: allocation-free rule) ----
__device__ __half g_F[(size_t)BATCH * KD];
__device__ __half g_W[(size_t)OUTF * KD];

// ---------------------------------------------------------------------------
// prep_f: cubic B-spline basis + silu -> fp16, 4 elems/thread.
// K layout k = n*INF + i; 4 adjacent i -> 8-byte packed stores.
// Uniform grid (h = 0.4): denominators are compile-time reciprocals.
// ---------------------------------------------------------------------------
__global__ void prep_f_kernel(const float* __restrict__ x,
                              const float* __restrict__ grid) {
    int t = blockIdx.x * blockDim.x + threadIdx.x;     // 0 .. 65535
    if (t >= BATCH * INF / 4) return;
    int b  = t >> 6;
    int i4 = (t & 63) * 4;
    float4 xv4 = ((const float4*)x)[t];
    float xv[4] = {xv4.x, xv4.y, xv4.z, xv4.w};

    float g[12];
#pragma unroll
    for (int j = 0; j < 12; j++) g[j] = __ldg(grid + j);
    const float r1 = 2.5f, r2 = 1.25f, r3 = 0.83333333333f;

    float bas[4][11];
#pragma unroll
    for (int l = 0; l < 4; l++) {
        float v = xv[l];
#pragma unroll
        for (int j = 0; j < 11; j++)
            bas[l][j] = (v >= g[j] && v < g[j + 1]) ? 1.0f : 0.0f;
#pragma unroll
        for (int j = 0; j < 10; j++)
            bas[l][j] = (v - g[j]) * r1 * bas[l][j] + (g[j + 2] - v) * r1 * bas[l][j + 1];
#pragma unroll
        for (int j = 0; j < 9; j++)
            bas[l][j] = (v - g[j]) * r2 * bas[l][j] + (g[j + 3] - v) * r2 * bas[l][j + 1];
#pragma unroll
        for (int j = 0; j < 8; j++)
            bas[l][j] = (v - g[j]) * r3 * bas[l][j] + (g[j + 4] - v) * r3 * bas[l][j + 1];
        bas[l][7] += (v >= g[8]) ? 1.0f : 0.0f;
        bas[l][8] = __fdividef(v, 1.0f + __expf(-v));   // silu in slot 8
    }

    size_t rowb = (size_t)b * KD + i4;
#pragma unroll
    for (int n = 0; n < 9; n++) {
        __half2 h0 = __floats2half2_rn(bas[0][n], bas[1][n]);
        __half2 h1 = __floats2half2_rn(bas[2][n], bas[3][n]);
        uint2 hp;
        hp.x = *(uint32_t*)&h0; hp.y = *(uint32_t*)&h1;
        *(uint2*)&g_F[rowb + n * INF] = hp;
    }
}

// ---------------------------------------------------------------------------
// prep_w: W[o][n*INF+i] = coeff[o,i,n]*spline_w[o,i] (n<8); [8*INF+i]=base_w.
// ---------------------------------------------------------------------------
__global__ void prep_w_kernel(const float* __restrict__ coeff,
                              const float* __restrict__ base_weight,
                              const float* __restrict__ spline_weight) {
    int t = blockIdx.x * blockDim.x + threadIdx.x;     // 0 .. 32767
    if (t >= OUTF * INF / 2) return;
    int o  = t >> 7;
    int i2 = (t & 127) * 2;

    float2 s2 = ((const float2*)spline_weight)[t];
    float2 bw = ((const float2*)base_weight)[t];
    const float4* c4 = (const float4*)(coeff + ((size_t)o * INF + i2) * 8);
    float4 a0 = c4[0], a1 = c4[1], a2 = c4[2], a3 = c4[3];
    float cv[2][9] = {
        {a0.x * s2.x, a0.y * s2.x, a0.z * s2.x, a0.w * s2.x,
         a1.x * s2.x, a1.y * s2.x, a1.z * s2.x, a1.w * s2.x, bw.x},
        {a2.x * s2.y, a2.y * s2.y, a2.z * s2.y, a2.w * s2.y,
         a3.x * s2.y, a3.y * s2.y, a3.z * s2.y, a3.w * s2.y, bw.y}};

    size_t rowb = (size_t)o * KD + i2;
#pragma unroll
    for (int n = 0; n < 9; n++) {
        __half2 hv = __floats2half2_rn(cv[0][n], cv[1][n]);
        *(__half2*)&g_W[rowb + n * INF] = hv;
    }
}

// ---------------------------------------------------------------------------
// GEMM: out = F * W^T, fp16 in / fp32 accum, full K = 2304 per CTA.
// BM=64 BN=32, 8 warps (4M x 2N, warp tile 16x16), NO split-K:
// grid (16,8) = 128 CTAs = 128 output tiles, direct store to out.
// 4-stage cp.async pipeline, XOR-swizzled smem.
// ---------------------------------------------------------------------------
#define A_TILE_B (BM * 64)      // 4096
#define B_TILE_B (BN * 64)      // 2048
#define STAGE_B  (A_TILE_B + B_TILE_B)

#define CP16(dst_u32, src_ptr) \
    asm volatile("cp.async.cg.shared.global [%0], [%1], 16;\n" \
                 :: "r"(dst_u32), "l"(src_ptr))

#define LDMX4(r0,r1,r2,r3, addr) \
    asm volatile("ldmatrix.sync.aligned.m8n8.x4.shared.b16 {%0,%1,%2,%3}, [%4];\n" \
                 : "=r"(r0),"=r"(r1),"=r"(r2),"=r"(r3) : "r"(addr))

#define MMA_F16(d, a, b0_, b1_) \
    asm volatile("mma.sync.aligned.m16n8k16.row.col.f32.f16.f16.f32 " \
                 "{%0,%1,%2,%3},{%4,%5,%6,%7},{%8,%9},{%0,%1,%2,%3};\n" \
                 : "+f"(d[0]),"+f"(d[1]),"+f"(d[2]),"+f"(d[3]) \
                 : "r"(a[0]),"r"(a[1]),"r"(a[2]),"r"(a[3]),"r"(b0_),"r"(b1_))

__global__ __launch_bounds__(256, 1)
void gemm_kernel(float* __restrict__ out) {
    __shared__ __align__(16) uint8_t smem[NSTAGE * STAGE_B];   // 24 KB

    const int tid  = threadIdx.x;
    const int warp = tid >> 5;
    const int lane = tid & 31;
    const int bm = blockIdx.x * BM;
    const int bn = blockIdx.y * BN;
    const int wm = (warp >> 1) * 16;    // 0,16,32,48
    const int wn = (warp & 1) * 16;     // 0,16

    const uint32_t smem_u32 = (uint32_t)__cvta_generic_to_shared(smem);

    auto load_tile = [&](int stage, int it) {
        int k0 = it * BK;
        uint32_t sA = smem_u32 + stage * STAGE_B;
        uint32_t sB = sA + A_TILE_B;
        {   // A: 256 16B chunks, exactly one per thread
            int row = tid >> 2, c = tid & 3;
            const __half* gp = g_F + (size_t)(bm + row) * KD + k0 + c * 8;
            uint32_t d = sA + (uint32_t)((row * 4 + (c ^ ((row >> 1) & 3))) << 4);
            CP16(d, gp);
        }
        if (tid < 128) {   // B: 128 chunks
            int row = tid >> 2, c = tid & 3;
            const __half* gp = g_W + (size_t)(bn + row) * KD + k0 + c * 8;
            uint32_t d = sB + (uint32_t)((row * 4 + (c ^ ((row >> 1) & 3))) << 4);
            CP16(d, gp);
        }
        asm volatile("cp.async.commit_group;\n" ::);
    };

    float acc[2][4];
#pragma unroll
    for (int b = 0; b < 2; b++)
#pragma unroll
        for (int c = 0; c < 4; c++) acc[b][c] = 0.0f;

    load_tile(0, 0);
    load_tile(1, 1);
    load_tile(2, 2);

    for (int t = 0; t < NT; t++) {
        int nx = t + NSTAGE - 1;
        if (nx < NT) load_tile((t + 3) % NSTAGE, nx);
        else asm volatile("cp.async.commit_group;\n" ::);
        asm volatile("cp.async.wait_group 3;\n" ::);
        __syncthreads();

        int stage = t % NSTAGE;
        uint32_t aBase = smem_u32 + stage * STAGE_B;
        uint32_t bBase = aBase + A_TILE_B;

#pragma unroll
        for (int kk = 0; kk < 2; kk++) {
            uint32_t afr[4];
            {
                int row = wm + (lane & 15);
                int ch  = kk * 2 + (lane >> 4);
                uint32_t ad = aBase + (uint32_t)((row * 4 + (ch ^ ((row >> 1) & 3))) << 4);
                LDMX4(afr[0], afr[1], afr[2], afr[3], ad);
            }
            uint32_t bfr[4];
            {
                int row = wn + ((lane >> 4) << 3) + (lane & 7);
                int ch  = kk * 2 + ((lane >> 3) & 1);
                uint32_t ad = bBase + (uint32_t)((row * 4 + (ch ^ ((row >> 1) & 3))) << 4);
                LDMX4(bfr[0], bfr[1], bfr[2], bfr[3], ad);
            }
            MMA_F16(acc[0], afr, bfr[0], bfr[1]);
            MMA_F16(acc[1], afr, bfr[2], bfr[3]);
        }
        __syncthreads();
    }

    // ---- epilogue: direct store to out ----
    const int g2 = lane >> 2, tg = lane & 3;
#pragma unroll
    for (int nt = 0; nt < 2; nt++) {
        int r  = bm + wm + g2;
        int cc = bn + wn + nt * 8 + tg * 2;
        *(float2*)&out[(size_t)r * OUTF + cc] = make_float2(acc[nt][0], acc[nt][1]);
        *(float2*)&out[(size_t)(r + 8) * OUTF + cc] = make_float2(acc[nt][2], acc[nt][3]);
    }
}

// ---------------------------------------------------------------------------
extern "C" void kernel_launch(void* const* d_in, const int* in_sizes, int n_in,
                              void* d_out, int out_size) {
    const float* x             = (const float*)d_in[0];
    const float* grid          = (const float*)d_in[1];
    const float* coeff         = (const float*)d_in[2];
    const float* base_weight   = (const float*)d_in[3];
    const float* spline_weight = (const float*)d_in[4];
    float* out = (float*)d_out;

    prep_f_kernel<<<(BATCH * INF / 4 + 255) / 256, 256>>>(x, grid);
    prep_w_kernel<<<(OUTF * INF / 2 + 255) / 256, 256>>>(coeff, base_weight, spline_weight);

    dim3 g(BATCH / BM, OUTF / BN);
    gemm_kernel<<<g, 256>>>(out);
}